// round 4
// baseline (speedup 1.0000x reference)
#include <cuda_runtime.h>
#include <cuda_fp16.h>
#include <stdint.h>
#include <math.h>

#define DF 128
#define LDS_A  136   // A-tile stride, fp16 elems (272B rows = odd*16B -> conflict-free ldmatrix)
#define LDS_W1 264   // W1/U1 stride (528B rows)
#define LDS_W2 136
#define ROWS_PER_BLK 256
#define MAX_N 50000

// Scratch (device globals are the sanctioned scratch mechanism)
__device__ float g_agg[MAX_N * DF];
__device__ int   g_idx64;

// ---------------- helpers ----------------
__device__ __forceinline__ float silu_f(float x) {
    return x / (1.0f + __expf(-x));
}

__device__ __forceinline__ void ldsm_x4(uint32_t& r0, uint32_t& r1, uint32_t& r2, uint32_t& r3,
                                        uint32_t addr) {
    asm volatile("ldmatrix.sync.aligned.m8n8.x4.shared.b16 {%0,%1,%2,%3}, [%4];"
                 : "=r"(r0), "=r"(r1), "=r"(r2), "=r"(r3) : "r"(addr));
}

__device__ __forceinline__ void mma16816(float* c, const uint32_t* a, uint32_t b0, uint32_t b1) {
    asm volatile("mma.sync.aligned.m16n8k16.row.col.f32.f16.f16.f32 "
                 "{%0,%1,%2,%3}, {%4,%5,%6,%7}, {%8,%9}, {%0,%1,%2,%3};"
                 : "+f"(c[0]), "+f"(c[1]), "+f"(c[2]), "+f"(c[3])
                 : "r"(a[0]), "r"(a[1]), "r"(a[2]), "r"(a[3]), "r"(b0), "r"(b1));
}

__device__ __forceinline__ void red_add_v2(float* p, float a, float b) {
    asm volatile("red.global.add.v2.f32 [%0], {%1,%2};" :: "l"(p), "f"(a), "f"(b) : "memory");
}

// Gather 32 rows (128 floats each) of tbl into fp16 A-tile rows [rbase, rbase+32)
__device__ __forceinline__ void gather_rows(const float* __restrict__ tbl, int gidx,
                                            __half* At, int rbase, int lane)
{
    #pragma unroll 4
    for (int ri = 0; ri < 32; ++ri) {
        int src = __shfl_sync(0xffffffffu, gidx, ri);
        float4 v = *reinterpret_cast<const float4*>(tbl + (size_t)src * DF + lane * 4);
        __half2 p0 = __floats2half2_rn(v.x, v.y);
        __half2 p1 = __floats2half2_rn(v.z, v.w);
        uint2 pk;
        pk.x = *reinterpret_cast<uint32_t*>(&p0);
        pk.y = *reinterpret_cast<uint32_t*>(&p1);
        *reinterpret_cast<uint2*>(&At[(rbase + ri) * LDS_A + lane * 4]) = pk;
    }
}

// One K=128 GEMM sweep: C[32 rows x 128 cols] += A(rows, k 0..127) * W(n, kg_w + k)
__device__ __forceinline__ void gemm_k128(float C[2][16][4], uint32_t At_addr, uint32_t W_addr,
                                          int ldw, int rbase, int lane, int kg_w)
{
    #pragma unroll 1
    for (int kt = 0; kt < 8; ++kt) {
        uint32_t a[2][4];
        #pragma unroll
        for (int ms = 0; ms < 2; ++ms) {
            int ar = rbase + ms * 16 + (lane & 7) + ((lane >> 3) & 1) * 8;
            int ac = kt * 16 + (lane >> 4) * 8;
            ldsm_x4(a[ms][0], a[ms][1], a[ms][2], a[ms][3],
                    At_addr + (uint32_t)((ar * LDS_A + ac) * 2));
        }
        #pragma unroll
        for (int np = 0; np < 8; ++np) {
            int br = np * 16 + (lane & 7) + (lane >> 4) * 8;
            int bc = kg_w + kt * 16 + ((lane >> 3) & 1) * 8;
            uint32_t b0, b1, b2, b3;
            ldsm_x4(b0, b1, b2, b3, W_addr + (uint32_t)((br * ldw + bc) * 2));
            mma16816(C[0][2 * np],     a[0], b0, b1);
            mma16816(C[0][2 * np + 1], a[0], b2, b3);
            mma16816(C[1][2 * np],     a[1], b0, b1);
            mma16816(C[1][2 * np + 1], a[1], b2, b3);
        }
    }
}

// ---------------- kernels ----------------

// detect int32 vs int64 edge_index: for int64 values < 2^31, every odd 32-bit word is 0
__global__ void detect_idx_kernel(const unsigned* __restrict__ p) {
    int all0 = 1;
    for (int i = 1; i < 64; i += 2) all0 &= (p[i] == 0u);
    g_idx64 = all0;
}

__global__ void zero_agg_kernel(int n4) {
    int i = blockIdx.x * blockDim.x + threadIdx.x;
    if (i < n4) reinterpret_cast<float4*>(g_agg)[i] = make_float4(0.f, 0.f, 0.f, 0.f);
}

#define SMEM_EDGE 175616
#define SMEM_NODE 173056

__global__ void __launch_bounds__(256, 1)
edge_kernel(const float* __restrict__ h, const float* __restrict__ coords,
            const void* __restrict__ eidx_raw,
            const float* __restrict__ W1, const float* __restrict__ b1,
            const float* __restrict__ W2, const float* __restrict__ b2,
            int nE)
{
    extern __shared__ __align__(16) unsigned char smem[];
    __half* W1s = (__half*)smem;                 // 128*264*2 = 67584
    __half* W2s = (__half*)(smem + 67584);       // 128*136*2 = 34816 -> 102400
    __half* At  = (__half*)(smem + 102400);      // 256*136*2 = 69632 -> 172032
    float* w1l    = (float*)(smem + 172032);     // 128
    float* b1s    = w1l + 128;
    float* b2s    = b1s + 128;
    float* dist_s = b2s + 128;                   // 256
    int*   ridx_s = (int*)(dist_s + 256);        // 256

    int tid = threadIdx.x;

    // weights -> SMEM (fp16); W1 col 256 (dist weight) kept fp32
    for (int i = tid; i < 128 * 257; i += 256) {
        int n = i / 257, k = i - n * 257;
        float v = W1[i];
        if (k < 256) W1s[n * LDS_W1 + k] = __float2half_rn(v);
        else         w1l[n] = v;
    }
    for (int i = tid; i < 128 * 128; i += 256)
        W2s[(i >> 7) * LDS_W2 + (i & 127)] = __float2half_rn(W2[i]);
    if (tid < 128) { b1s[tid] = b1[tid]; b2s[tid] = b2[tid]; }

    int lane = tid & 31, warp = tid >> 5;
    int rbase = warp * 32;
    long long e0 = (long long)blockIdx.x * ROWS_PER_BLK + rbase;

    // per-lane edge metadata (lane = edge within warp-tile)
    int sidx = 0, ridx = -1;
    {
        long long e = e0 + lane;
        if (e < (long long)nE) {
            if (g_idx64) {
                const long long* p = (const long long*)eidx_raw;
                sidx = (int)p[e]; ridx = (int)p[(long long)nE + e];
            } else {
                const int* p = (const int*)eidx_raw;
                sidx = p[e]; ridx = p[nE + e];
            }
        }
        float dd = 0.f;
        if (ridx >= 0) {
            float dx = coords[sidx * 3 + 0] - coords[ridx * 3 + 0];
            float dy = coords[sidx * 3 + 1] - coords[ridx * 3 + 1];
            float dz = coords[sidx * 3 + 2] - coords[ridx * 3 + 2];
            dd = sqrtf(dx * dx + dy * dy + dz * dz);
        }
        dist_s[rbase + lane] = dd;
        ridx_s[rbase + lane] = ridx;
    }
    __syncthreads();  // weights ready

    uint32_t At_addr = (uint32_t)__cvta_generic_to_shared(At);
    uint32_t W1_addr = (uint32_t)__cvta_generic_to_shared(W1s);
    uint32_t W2_addr = (uint32_t)__cvta_generic_to_shared(W2s);

    float C[2][16][4];
    #pragma unroll
    for (int ms = 0; ms < 2; ++ms)
        #pragma unroll
        for (int nt = 0; nt < 16; ++nt)
            #pragma unroll
            for (int j = 0; j < 4; ++j) C[ms][nt][j] = 0.f;

    // ---- GEMM1: K = 256 in two halves (h_sender then h_receiver) ----
    for (int half = 0; half < 2; ++half) {
        int gidx = (half == 0) ? sidx : (ridx < 0 ? 0 : ridx);
        gather_rows(h, gidx, At, rbase, lane);
        __syncwarp();
        gemm_k128(C, At_addr, W1_addr, LDS_W1, rbase, lane, half * 128);
        __syncwarp();  // before next half overwrites this warp's A rows
    }

    // ---- epilogue 1: + dist * w1_last + b1, SiLU, fp16 -> A-tile; reset C ----
    int qr = lane >> 2;
    int qc = (lane & 3) * 2;
    #pragma unroll
    for (int ms = 0; ms < 2; ++ms) {
        int r0 = rbase + ms * 16 + qr;
        float dA = dist_s[r0], dB = dist_s[r0 + 8];
        #pragma unroll
        for (int nt = 0; nt < 16; ++nt) {
            int col = nt * 8 + qc;
            float w0 = w1l[col], w1v = w1l[col + 1];
            float bb0 = b1s[col], bb1 = b1s[col + 1];
            float x0 = silu_f(C[ms][nt][0] + dA * w0 + bb0);
            float x1 = silu_f(C[ms][nt][1] + dA * w1v + bb1);
            float x2 = silu_f(C[ms][nt][2] + dB * w0 + bb0);
            float x3 = silu_f(C[ms][nt][3] + dB * w1v + bb1);
            __half2 p0 = __floats2half2_rn(x0, x1);
            __half2 p1 = __floats2half2_rn(x2, x3);
            *reinterpret_cast<uint32_t*>(&At[r0 * LDS_A + col])       = *reinterpret_cast<uint32_t*>(&p0);
            *reinterpret_cast<uint32_t*>(&At[(r0 + 8) * LDS_A + col]) = *reinterpret_cast<uint32_t*>(&p1);
            C[ms][nt][0] = 0.f; C[ms][nt][1] = 0.f; C[ms][nt][2] = 0.f; C[ms][nt][3] = 0.f;
        }
    }
    __syncwarp();

    // ---- GEMM2: K = 128 with W2 ----
    gemm_k128(C, At_addr, W2_addr, LDS_W2, rbase, lane, 0);

    // ---- epilogue 2: SiLU then scatter-add into g_agg[receiver] ----
    #pragma unroll
    for (int ms = 0; ms < 2; ++ms) {
        int r0 = rbase + ms * 16 + qr;
        int iA = ridx_s[r0], iB = ridx_s[r0 + 8];
        #pragma unroll
        for (int nt = 0; nt < 16; ++nt) {
            int col = nt * 8 + qc;
            float bb0 = b2s[col], bb1 = b2s[col + 1];
            float x0 = silu_f(C[ms][nt][0] + bb0);
            float x1 = silu_f(C[ms][nt][1] + bb1);
            float x2 = silu_f(C[ms][nt][2] + bb0);
            float x3 = silu_f(C[ms][nt][3] + bb1);
            if (iA >= 0) red_add_v2(&g_agg[(size_t)iA * DF + col], x0, x1);
            if (iB >= 0) red_add_v2(&g_agg[(size_t)iB * DF + col], x2, x3);
        }
    }
}

__global__ void __launch_bounds__(256, 1)
node_kernel(const float* __restrict__ h,
            const float* __restrict__ U1, const float* __restrict__ c1,
            const float* __restrict__ U2, const float* __restrict__ c2,
            float* __restrict__ out, int nN)
{
    extern __shared__ __align__(16) unsigned char smem[];
    __half* U1s = (__half*)smem;                 // 67584
    __half* U2s = (__half*)(smem + 67584);       // 34816 -> 102400
    __half* At  = (__half*)(smem + 102400);      // 69632 -> 172032
    float* c1s = (float*)(smem + 172032);
    float* c2s = c1s + 128;

    int tid = threadIdx.x;
    for (int i = tid; i < 128 * 256; i += 256)
        U1s[(i >> 8) * LDS_W1 + (i & 255)] = __float2half_rn(U1[i]);
    for (int i = tid; i < 128 * 128; i += 256)
        U2s[(i >> 7) * LDS_W2 + (i & 127)] = __float2half_rn(U2[i]);
    if (tid < 128) { c1s[tid] = c1[tid]; c2s[tid] = c2[tid]; }
    __syncthreads();

    int lane = tid & 31, warp = tid >> 5;
    int rbase = warp * 32;
    int blockbase = blockIdx.x * ROWS_PER_BLK;

    uint32_t At_addr = (uint32_t)__cvta_generic_to_shared(At);
    uint32_t U1_addr = (uint32_t)__cvta_generic_to_shared(U1s);
    uint32_t U2_addr = (uint32_t)__cvta_generic_to_shared(U2s);

    float C[2][16][4];
    #pragma unroll
    for (int ms = 0; ms < 2; ++ms)
        #pragma unroll
        for (int nt = 0; nt < 16; ++nt)
            #pragma unroll
            for (int j = 0; j < 4; ++j) C[ms][nt][j] = 0.f;

    // ---- GEMM1: u_in = [h | agg], K = 256 ----
    for (int half = 0; half < 2; ++half) {
        const float* tbl = (half == 0) ? h : g_agg;
        #pragma unroll 4
        for (int ri = 0; ri < 32; ++ri) {
            int node = blockbase + rbase + ri;
            if (node >= nN) node = nN - 1;
            float4 v = *reinterpret_cast<const float4*>(tbl + (size_t)node * DF + lane * 4);
            __half2 p0 = __floats2half2_rn(v.x, v.y);
            __half2 p1 = __floats2half2_rn(v.z, v.w);
            uint2 pk;
            pk.x = *reinterpret_cast<uint32_t*>(&p0);
            pk.y = *reinterpret_cast<uint32_t*>(&p1);
            *reinterpret_cast<uint2*>(&At[(rbase + ri) * LDS_A + lane * 4]) = pk;
        }
        __syncwarp();
        gemm_k128(C, At_addr, U1_addr, LDS_W1, rbase, lane, half * 128);
        __syncwarp();
    }

    int qr = lane >> 2;
    int qc = (lane & 3) * 2;

    // ---- epilogue 1: SiLU(C + c1), fp16 -> A-tile; reset C ----
    #pragma unroll
    for (int ms = 0; ms < 2; ++ms) {
        int r0 = rbase + ms * 16 + qr;
        #pragma unroll
        for (int nt = 0; nt < 16; ++nt) {
            int col = nt * 8 + qc;
            float bb0 = c1s[col], bb1 = c1s[col + 1];
            float x0 = silu_f(C[ms][nt][0] + bb0);
            float x1 = silu_f(C[ms][nt][1] + bb1);
            float x2 = silu_f(C[ms][nt][2] + bb0);
            float x3 = silu_f(C[ms][nt][3] + bb1);
            __half2 p0 = __floats2half2_rn(x0, x1);
            __half2 p1 = __floats2half2_rn(x2, x3);
            *reinterpret_cast<uint32_t*>(&At[r0 * LDS_A + col])       = *reinterpret_cast<uint32_t*>(&p0);
            *reinterpret_cast<uint32_t*>(&At[(r0 + 8) * LDS_A + col]) = *reinterpret_cast<uint32_t*>(&p1);
            C[ms][nt][0] = 0.f; C[ms][nt][1] = 0.f; C[ms][nt][2] = 0.f; C[ms][nt][3] = 0.f;
        }
    }
    __syncwarp();

    // ---- GEMM2: K = 128 with U2 ----
    gemm_k128(C, At_addr, U2_addr, LDS_W2, rbase, lane, 0);

    // ---- epilogue 2: out = h + (C + c2) ----
    #pragma unroll
    for (int ms = 0; ms < 2; ++ms) {
        int r0 = rbase + ms * 16 + qr;
        int nodeA = blockbase + r0;
        int nodeB = nodeA + 8;
        #pragma unroll
        for (int nt = 0; nt < 16; ++nt) {
            int col = nt * 8 + qc;
            float bb0 = c2s[col], bb1 = c2s[col + 1];
            if (nodeA < nN) {
                float2 hv = *reinterpret_cast<const float2*>(h + (size_t)nodeA * DF + col);
                float2 o;
                o.x = hv.x + C[ms][nt][0] + bb0;
                o.y = hv.y + C[ms][nt][1] + bb1;
                *reinterpret_cast<float2*>(out + (size_t)nodeA * DF + col) = o;
            }
            if (nodeB < nN) {
                float2 hv = *reinterpret_cast<const float2*>(h + (size_t)nodeB * DF + col);
                float2 o;
                o.x = hv.x + C[ms][nt][2] + bb0;
                o.y = hv.y + C[ms][nt][3] + bb1;
                *reinterpret_cast<float2*>(out + (size_t)nodeB * DF + col) = o;
            }
        }
    }
}

// ---------------- launch ----------------
extern "C" void kernel_launch(void* const* d_in, const int* in_sizes, int n_in,
                              void* d_out, int out_size)
{
    const float* h      = (const float*)d_in[0];
    const float* coords = (const float*)d_in[1];
    const void*  eidx   = d_in[2];
    const float* W1     = (const float*)d_in[3];
    const float* b1     = (const float*)d_in[4];
    const float* W2     = (const float*)d_in[5];
    const float* b2     = (const float*)d_in[6];
    const float* U1     = (const float*)d_in[7];
    const float* c1     = (const float*)d_in[8];
    const float* U2     = (const float*)d_in[9];
    const float* c2     = (const float*)d_in[10];
    float* out = (float*)d_out;

    int nN = in_sizes[0] / DF;
    int nE = in_sizes[2] / 2;

    cudaFuncSetAttribute(edge_kernel, cudaFuncAttributeMaxDynamicSharedMemorySize, SMEM_EDGE);
    cudaFuncSetAttribute(node_kernel, cudaFuncAttributeMaxDynamicSharedMemorySize, SMEM_NODE);

    detect_idx_kernel<<<1, 1>>>((const unsigned*)eidx);

    int n4 = nN * DF / 4;
    zero_agg_kernel<<<(n4 + 255) / 256, 256>>>(n4);

    int gE = (nE + ROWS_PER_BLK - 1) / ROWS_PER_BLK;
    edge_kernel<<<gE, 256, SMEM_EDGE>>>(h, coords, eidx, W1, b1, W2, b2, nE);

    int gN = (nN + ROWS_PER_BLK - 1) / ROWS_PER_BLK;
    node_kernel<<<gN, 256, SMEM_NODE>>>(h, U1, c1, U2, c2, out, nN);
}

// round 6
// speedup vs baseline: 1.9664x; 1.9664x over previous
#include <cuda_runtime.h>
#include <cuda_fp16.h>
#include <stdint.h>
#include <math.h>

#define DF 128
#define LDS_A  136   // A-tile stride (272B rows -> conflict-free ldmatrix)
#define LDS_W1 264   // W1/U1 stride (528B rows)
#define LDS_W2 136
#define TILE_E 256   // edges (or nodes) per block-tile
#define MAX_N 50000

// Scratch (device globals are the sanctioned scratch mechanism)
__device__ float  g_agg[MAX_N * DF];
__device__ __half g_h16[MAX_N * DF];
__device__ int    g_idx64;

// ---------------- helpers ----------------
__device__ __forceinline__ float silu_f(float x) {
    return x / (1.0f + __expf(-x));
}

__device__ __forceinline__ void ldsm_x4(uint32_t& r0, uint32_t& r1, uint32_t& r2, uint32_t& r3,
                                        uint32_t addr) {
    asm volatile("ldmatrix.sync.aligned.m8n8.x4.shared.b16 {%0,%1,%2,%3}, [%4];"
                 : "=r"(r0), "=r"(r1), "=r"(r2), "=r"(r3) : "r"(addr));
}

__device__ __forceinline__ void mma16816(float* c, const uint32_t* a, uint32_t b0, uint32_t b1) {
    asm volatile("mma.sync.aligned.m16n8k16.row.col.f32.f16.f16.f32 "
                 "{%0,%1,%2,%3}, {%4,%5,%6,%7}, {%8,%9}, {%0,%1,%2,%3};"
                 : "+f"(c[0]), "+f"(c[1]), "+f"(c[2]), "+f"(c[3])
                 : "r"(a[0]), "r"(a[1]), "r"(a[2]), "r"(a[3]), "r"(b0), "r"(b1));
}

__device__ __forceinline__ void red_add_v2(float* p, float a, float b) {
    asm volatile("red.global.add.v2.f32 [%0], {%1,%2};" :: "l"(p), "f"(a), "f"(b) : "memory");
}

__device__ __forceinline__ void cp_async8(uint32_t dst, const void* src) {
    asm volatile("cp.async.ca.shared.global [%0], [%1], 8;" :: "r"(dst), "l"(src));
}
__device__ __forceinline__ void cp_commit_wait() {
    asm volatile("cp.async.commit_group;");
    asm volatile("cp.async.wait_group 0;" ::: "memory");
}
__device__ __forceinline__ void pair_bar(int barid) {
    asm volatile("bar.sync %0, 64;" :: "r"(barid) : "memory");
}

// Warp GEMM: C[32 rows x 64 cols] += A(rows rbase.., k 0..127) * W(n0.., kg_w + k)
__device__ __forceinline__ void gemm_pair(float C[2][8][4], uint32_t At_addr, uint32_t W_addr,
                                          int ldw, int rbase, int n0, int lane, int kg_w)
{
    #pragma unroll
    for (int kt = 0; kt < 8; ++kt) {
        uint32_t a[2][4];
        #pragma unroll
        for (int ms = 0; ms < 2; ++ms) {
            int ar = rbase + ms * 16 + (lane & 7) + ((lane >> 3) & 1) * 8;
            int ac = kt * 16 + (lane >> 4) * 8;
            ldsm_x4(a[ms][0], a[ms][1], a[ms][2], a[ms][3],
                    At_addr + (uint32_t)((ar * LDS_A + ac) * 2));
        }
        #pragma unroll
        for (int np = 0; np < 4; ++np) {
            int br = n0 + np * 16 + (lane & 7) + (lane >> 4) * 8;
            int bc = kg_w + kt * 16 + ((lane >> 3) & 1) * 8;
            uint32_t b0, b1, b2, b3;
            ldsm_x4(b0, b1, b2, b3, W_addr + (uint32_t)((br * ldw + bc) * 2));
            mma16816(C[0][2 * np],     a[0], b0, b1);
            mma16816(C[0][2 * np + 1], a[0], b2, b3);
            mma16816(C[1][2 * np],     a[1], b0, b1);
            mma16816(C[1][2 * np + 1], a[1], b2, b3);
        }
    }
}

// ---------------- small kernels ----------------
__global__ void detect_idx_kernel(const unsigned* __restrict__ p) {
    int all0 = 1;
    for (int i = 1; i < 64; i += 2) all0 &= (p[i] == 0u);
    g_idx64 = all0;
}

__global__ void zero_agg_kernel(int n4) {
    int i = blockIdx.x * blockDim.x + threadIdx.x;
    if (i < n4) reinterpret_cast<float4*>(g_agg)[i] = make_float4(0.f, 0.f, 0.f, 0.f);
}

__global__ void prep_h16_kernel(const float* __restrict__ h, int n4) {
    int i = blockIdx.x * blockDim.x + threadIdx.x;
    if (i < n4) {
        float4 v = reinterpret_cast<const float4*>(h)[i];
        __half2 p0 = __floats2half2_rn(v.x, v.y);
        __half2 p1 = __floats2half2_rn(v.z, v.w);
        uint2 pk;
        pk.x = *reinterpret_cast<uint32_t*>(&p0);
        pk.y = *reinterpret_cast<uint32_t*>(&p1);
        reinterpret_cast<uint2*>(g_h16)[i] = pk;
    }
}

#define SMEM_EDGE 175616
#define SMEM_NODE 173056

// ---------------- edge kernel (persistent, 512 threads, warp-pairs) ----------------
__global__ void __launch_bounds__(512, 1)
edge_kernel(const float* __restrict__ coords, const void* __restrict__ eidx_raw,
            const float* __restrict__ W1, const float* __restrict__ b1,
            const float* __restrict__ W2, const float* __restrict__ b2,
            int nE, int nTiles)
{
    extern __shared__ __align__(16) unsigned char smem[];
    __half* W1s = (__half*)smem;                 // 67584
    __half* W2s = (__half*)(smem + 67584);       // 34816 -> 102400
    __half* At  = (__half*)(smem + 102400);      // 256*136*2 = 69632 -> 172032
    float* w1l    = (float*)(smem + 172032);     // 128 (pad 512B)
    float* b1s    = (float*)(smem + 172544);
    float* b2s    = (float*)(smem + 173056);
    float* dist_s = (float*)(smem + 173568);     // 256
    int*   ridx_s = (int*)  (smem + 174592);     // 256

    int tid = threadIdx.x;

    // weights -> SMEM once (fp16); W1 col 256 (dist weight) kept fp32
    for (int i = tid; i < 128 * 257; i += 512) {
        int n = i / 257, k = i - n * 257;
        float v = W1[i];
        if (k < 256) W1s[n * LDS_W1 + k] = __float2half_rn(v);
        else         w1l[n] = v;
    }
    for (int i = tid; i < 128 * 128; i += 512)
        W2s[(i >> 7) * LDS_W2 + (i & 127)] = __float2half_rn(W2[i]);
    if (tid < 128) { b1s[tid] = b1[tid]; b2s[tid] = b2[tid]; }
    __syncthreads();

    const int lane = tid & 31, warp = tid >> 5;
    const int pair = warp >> 1, wsub = warp & 1;
    const int barid = pair + 1;
    const int rbase = pair * 32;
    const int n0 = wsub * 64;
    const bool idx64 = (g_idx64 != 0);

    uint32_t At_addr = (uint32_t)__cvta_generic_to_shared(At);
    uint32_t W1_addr = (uint32_t)__cvta_generic_to_shared(W1s);
    uint32_t W2_addr = (uint32_t)__cvta_generic_to_shared(W2s);

    const int qr = lane >> 2;
    const int qc = (lane & 3) * 2;

    for (int tile = blockIdx.x; tile < nTiles; tile += gridDim.x) {
        pair_bar(barid);  // previous tile fully consumed (At, dist_s, ridx_s)

        long long e0 = (long long)tile * TILE_E;

        // ---- meta: this warp owns 16 edges (duplicated across lane halves) ----
        int lane16 = lane & 15;
        long long e = e0 + rbase + wsub * 16 + lane16;
        int sidx = 0, ridx = -1;
        if (e < (long long)nE) {
            if (idx64) {
                const long long* p = (const long long*)eidx_raw;
                sidx = (int)p[e]; ridx = (int)p[(long long)nE + e];
            } else {
                const int* p = (const int*)eidx_raw;
                sidx = p[e]; ridx = p[nE + e];
            }
        }
        float dd = 0.f;
        if (ridx >= 0) {
            float dx = coords[sidx * 3 + 0] - coords[ridx * 3 + 0];
            float dy = coords[sidx * 3 + 1] - coords[ridx * 3 + 1];
            float dz = coords[sidx * 3 + 2] - coords[ridx * 3 + 2];
            dd = sqrtf(dx * dx + dy * dy + dz * dz);
        }
        if (lane < 16) {
            int rr = rbase + wsub * 16 + lane;
            dist_s[rr] = dd;
            ridx_s[rr] = ridx;
        }

        float C[2][8][4];
        #pragma unroll
        for (int ms = 0; ms < 2; ++ms)
            #pragma unroll
            for (int nt = 0; nt < 8; ++nt)
                #pragma unroll
                for (int j = 0; j < 4; ++j) C[ms][nt][j] = 0.f;

        // ---- gather sender rows (this warp's 16) via cp.async from fp16 h ----
        #pragma unroll 4
        for (int ri = 0; ri < 16; ++ri) {
            int src = __shfl_sync(0xffffffffu, sidx, ri);
            int row = rbase + wsub * 16 + ri;
            cp_async8(At_addr + (uint32_t)((row * LDS_A + lane * 4) * 2),
                      g_h16 + (size_t)src * DF + lane * 4);
        }
        cp_commit_wait();
        pair_bar(barid);

        gemm_pair(C, At_addr, W1_addr, LDS_W1, rbase, n0, lane, 0);
        pair_bar(barid);  // both warps done reading A before overwrite

        // ---- gather receiver rows ----
        int ridx_g = (ridx < 0) ? 0 : ridx;
        #pragma unroll 4
        for (int ri = 0; ri < 16; ++ri) {
            int src = __shfl_sync(0xffffffffu, ridx_g, ri);
            int row = rbase + wsub * 16 + ri;
            cp_async8(At_addr + (uint32_t)((row * LDS_A + lane * 4) * 2),
                      g_h16 + (size_t)src * DF + lane * 4);
        }
        cp_commit_wait();
        pair_bar(barid);

        gemm_pair(C, At_addr, W1_addr, LDS_W1, rbase, n0, lane, 128);
        pair_bar(barid);  // both warps done reading A before epilogue overwrite

        // ---- epilogue 1: + dist * w1_last + b1, SiLU, fp16 -> A-tile cols [n0,n0+64) ----
        #pragma unroll
        for (int ms = 0; ms < 2; ++ms) {
            int r0 = rbase + ms * 16 + qr;
            float dA = dist_s[r0], dB = dist_s[r0 + 8];
            #pragma unroll
            for (int nt = 0; nt < 8; ++nt) {
                int col = n0 + nt * 8 + qc;
                float w0 = w1l[col], w1v = w1l[col + 1];
                float bb0 = b1s[col], bb1 = b1s[col + 1];
                float x0 = silu_f(C[ms][nt][0] + dA * w0 + bb0);
                float x1 = silu_f(C[ms][nt][1] + dA * w1v + bb1);
                float x2 = silu_f(C[ms][nt][2] + dB * w0 + bb0);
                float x3 = silu_f(C[ms][nt][3] + dB * w1v + bb1);
                __half2 p0 = __floats2half2_rn(x0, x1);
                __half2 p1 = __floats2half2_rn(x2, x3);
                *reinterpret_cast<uint32_t*>(&At[r0 * LDS_A + col])       = *reinterpret_cast<uint32_t*>(&p0);
                *reinterpret_cast<uint32_t*>(&At[(r0 + 8) * LDS_A + col]) = *reinterpret_cast<uint32_t*>(&p1);
                C[ms][nt][0] = 0.f; C[ms][nt][1] = 0.f; C[ms][nt][2] = 0.f; C[ms][nt][3] = 0.f;
            }
        }
        pair_bar(barid);  // full 32x128 layer-1 output visible to both warps

        // ---- GEMM2: K=128 with W2 ----
        gemm_pair(C, At_addr, W2_addr, LDS_W2, rbase, n0, lane, 0);

        // ---- epilogue 2: SiLU then scatter-add into g_agg[receiver] ----
        #pragma unroll
        for (int ms = 0; ms < 2; ++ms) {
            int r0 = rbase + ms * 16 + qr;
            int iA = ridx_s[r0], iB = ridx_s[r0 + 8];
            #pragma unroll
            for (int nt = 0; nt < 8; ++nt) {
                int col = n0 + nt * 8 + qc;
                float bb0 = b2s[col], bb1 = b2s[col + 1];
                float x0 = silu_f(C[ms][nt][0] + bb0);
                float x1 = silu_f(C[ms][nt][1] + bb1);
                float x2 = silu_f(C[ms][nt][2] + bb0);
                float x3 = silu_f(C[ms][nt][3] + bb1);
                if (iA >= 0) red_add_v2(&g_agg[(size_t)iA * DF + col], x0, x1);
                if (iB >= 0) red_add_v2(&g_agg[(size_t)iB * DF + col], x2, x3);
            }
        }
    }
}

// ---------------- node kernel (persistent, 512 threads, warp-pairs) ----------------
__global__ void __launch_bounds__(512, 1)
node_kernel(const float* __restrict__ h,
            const float* __restrict__ U1, const float* __restrict__ c1,
            const float* __restrict__ U2, const float* __restrict__ c2,
            float* __restrict__ out, int nN, int nTiles)
{
    extern __shared__ __align__(16) unsigned char smem[];
    __half* U1s = (__half*)smem;                 // 67584
    __half* U2s = (__half*)(smem + 67584);       // -> 102400
    __half* At  = (__half*)(smem + 102400);      // -> 172032
    float* c1s = (float*)(smem + 172032);
    float* c2s = (float*)(smem + 172544);

    int tid = threadIdx.x;
    for (int i = tid; i < 128 * 256; i += 512)
        U1s[(i >> 8) * LDS_W1 + (i & 255)] = __float2half_rn(U1[i]);
    for (int i = tid; i < 128 * 128; i += 512)
        U2s[(i >> 7) * LDS_W2 + (i & 127)] = __float2half_rn(U2[i]);
    if (tid < 128) { c1s[tid] = c1[tid]; c2s[tid] = c2[tid]; }
    __syncthreads();

    const int lane = tid & 31, warp = tid >> 5;
    const int pair = warp >> 1, wsub = warp & 1;
    const int barid = pair + 1;
    const int rbase = pair * 32;
    const int n0 = wsub * 64;

    uint32_t At_addr = (uint32_t)__cvta_generic_to_shared(At);
    uint32_t U1_addr = (uint32_t)__cvta_generic_to_shared(U1s);
    uint32_t U2_addr = (uint32_t)__cvta_generic_to_shared(U2s);

    const int qr = lane >> 2;
    const int qc = (lane & 3) * 2;

    for (int tile = blockIdx.x; tile < nTiles; tile += gridDim.x) {
        pair_bar(barid);
        int tbase = tile * TILE_E;

        float C[2][8][4];
        #pragma unroll
        for (int ms = 0; ms < 2; ++ms)
            #pragma unroll
            for (int nt = 0; nt < 8; ++nt)
                #pragma unroll
                for (int j = 0; j < 4; ++j) C[ms][nt][j] = 0.f;

        // ---- gather h rows (fp16 table, cp.async) ----
        #pragma unroll 4
        for (int ri = 0; ri < 16; ++ri) {
            int node = tbase + rbase + wsub * 16 + ri;
            if (node >= nN) node = nN - 1;
            int row = rbase + wsub * 16 + ri;
            cp_async8(At_addr + (uint32_t)((row * LDS_A + lane * 4) * 2),
                      g_h16 + (size_t)node * DF + lane * 4);
        }
        cp_commit_wait();
        pair_bar(barid);

        gemm_pair(C, At_addr, U1_addr, LDS_W1, rbase, n0, lane, 0);
        pair_bar(barid);

        // ---- gather agg rows (fp32 -> fp16) ----
        #pragma unroll 4
        for (int ri = 0; ri < 16; ++ri) {
            int node = tbase + rbase + wsub * 16 + ri;
            if (node >= nN) node = nN - 1;
            int row = rbase + wsub * 16 + ri;
            float4 v = *reinterpret_cast<const float4*>(g_agg + (size_t)node * DF + lane * 4);
            __half2 p0 = __floats2half2_rn(v.x, v.y);
            __half2 p1 = __floats2half2_rn(v.z, v.w);
            uint2 pk;
            pk.x = *reinterpret_cast<uint32_t*>(&p0);
            pk.y = *reinterpret_cast<uint32_t*>(&p1);
            *reinterpret_cast<uint2*>(&At[row * LDS_A + lane * 4]) = pk;
        }
        __syncwarp();
        pair_bar(barid);

        gemm_pair(C, At_addr, U1_addr, LDS_W1, rbase, n0, lane, 128);
        pair_bar(barid);

        // ---- epilogue 1: SiLU(C + c1) -> A-tile ----
        #pragma unroll
        for (int ms = 0; ms < 2; ++ms) {
            int r0 = rbase + ms * 16 + qr;
            #pragma unroll
            for (int nt = 0; nt < 8; ++nt) {
                int col = n0 + nt * 8 + qc;
                float bb0 = c1s[col], bb1 = c1s[col + 1];
                float x0 = silu_f(C[ms][nt][0] + bb0);
                float x1 = silu_f(C[ms][nt][1] + bb1);
                float x2 = silu_f(C[ms][nt][2] + bb0);
                float x3 = silu_f(C[ms][nt][3] + bb1);
                __half2 p0 = __floats2half2_rn(x0, x1);
                __half2 p1 = __floats2half2_rn(x2, x3);
                *reinterpret_cast<uint32_t*>(&At[r0 * LDS_A + col])       = *reinterpret_cast<uint32_t*>(&p0);
                *reinterpret_cast<uint32_t*>(&At[(r0 + 8) * LDS_A + col]) = *reinterpret_cast<uint32_t*>(&p1);
                C[ms][nt][0] = 0.f; C[ms][nt][1] = 0.f; C[ms][nt][2] = 0.f; C[ms][nt][3] = 0.f;
            }
        }
        pair_bar(barid);

        gemm_pair(C, At_addr, U2_addr, LDS_W2, rbase, n0, lane, 0);

        // ---- epilogue 2: out = h + (C + c2) ----
        #pragma unroll
        for (int ms = 0; ms < 2; ++ms) {
            int r0 = rbase + ms * 16 + qr;
            int nodeA = tbase + r0;
            int nodeB = nodeA + 8;
            #pragma unroll
            for (int nt = 0; nt < 8; ++nt) {
                int col = n0 + nt * 8 + qc;
                float bb0 = c2s[col], bb1 = c2s[col + 1];
                if (nodeA < nN) {
                    float2 hv = *reinterpret_cast<const float2*>(h + (size_t)nodeA * DF + col);
                    float2 o;
                    o.x = hv.x + C[ms][nt][0] + bb0;
                    o.y = hv.y + C[ms][nt][1] + bb1;
                    *reinterpret_cast<float2*>(out + (size_t)nodeA * DF + col) = o;
                }
                if (nodeB < nN) {
                    float2 hv = *reinterpret_cast<const float2*>(h + (size_t)nodeB * DF + col);
                    float2 o;
                    o.x = hv.x + C[ms][nt][2] + bb0;
                    o.y = hv.y + C[ms][nt][3] + bb1;
                    *reinterpret_cast<float2*>(out + (size_t)nodeB * DF + col) = o;
                }
            }
        }
    }
}

// ---------------- launch ----------------
extern "C" void kernel_launch(void* const* d_in, const int* in_sizes, int n_in,
                              void* d_out, int out_size)
{
    const float* h      = (const float*)d_in[0];
    const float* coords = (const float*)d_in[1];
    const void*  eidx   = d_in[2];
    const float* W1     = (const float*)d_in[3];
    const float* b1     = (const float*)d_in[4];
    const float* W2     = (const float*)d_in[5];
    const float* b2     = (const float*)d_in[6];
    const float* U1     = (const float*)d_in[7];
    const float* c1     = (const float*)d_in[8];
    const float* U2     = (const float*)d_in[9];
    const float* c2     = (const float*)d_in[10];
    float* out = (float*)d_out;

    int nN = in_sizes[0] / DF;
    int nE = in_sizes[2] / 2;

    int sms = 148;
    cudaDeviceGetAttribute(&sms, cudaDevAttrMultiProcessorCount, 0);

    cudaFuncSetAttribute(edge_kernel, cudaFuncAttributeMaxDynamicSharedMemorySize, SMEM_EDGE);
    cudaFuncSetAttribute(node_kernel, cudaFuncAttributeMaxDynamicSharedMemorySize, SMEM_NODE);

    detect_idx_kernel<<<1, 1>>>((const unsigned*)eidx);

    int n4 = nN * DF / 4;
    prep_h16_kernel<<<(n4 + 255) / 256, 256>>>(h, n4);
    zero_agg_kernel<<<(n4 + 255) / 256, 256>>>(n4);

    int nTilesE = (nE + TILE_E - 1) / TILE_E;
    int gE = (sms < nTilesE) ? sms : nTilesE;
    edge_kernel<<<gE, 512, SMEM_EDGE>>>(coords, eidx, W1, b1, W2, b2, nE, nTilesE);

    int nTilesN = (nN + TILE_E - 1) / TILE_E;
    int gN = (sms < nTilesN) ? sms : nTilesN;
    node_kernel<<<gN, 512, SMEM_NODE>>>(h, U1, c1, U2, c2, out, nN, nTilesN);
}

// round 9
// speedup vs baseline: 2.6810x; 1.3634x over previous
#include <cuda_runtime.h>
#include <cuda_fp16.h>
#include <stdint.h>
#include <math.h>

#define DF 128
#define LDS_A  136   // A-tile stride (272B rows -> conflict-free ldmatrix)
#define LDS_W1 264   // W1/U1 stride (528B rows)
#define LDS_W2 136
#define TILE_E 256   // edges (or nodes) per block-tile
#define MAX_N 50000

// Scratch (device globals are the sanctioned scratch mechanism)
__device__ float  g_agg[MAX_N * DF];
__device__ __half g_h16[MAX_N * DF];
__device__ int    g_idx64;

// ---------------- helpers ----------------
__device__ __forceinline__ __half2 silu_h2(__half2 x) {
    // silu(x) = x * sigmoid(x) = (x/2) * (1 + tanh(x/2))
    __half2 xh = __hmul2(x, __half2half2(__float2half(0.5f)));
    uint32_t xin = *reinterpret_cast<uint32_t*>(&xh), tout;
    asm("tanh.approx.f16x2 %0, %1;" : "=r"(tout) : "r"(xin));
    __half2 t = *reinterpret_cast<__half2*>(&tout);
    return __hfma2(xh, t, xh);
}

__device__ __forceinline__ void ldsm_x4(uint32_t& r0, uint32_t& r1, uint32_t& r2, uint32_t& r3,
                                        uint32_t addr) {
    asm volatile("ldmatrix.sync.aligned.m8n8.x4.shared.b16 {%0,%1,%2,%3}, [%4];"
                 : "=r"(r0), "=r"(r1), "=r"(r2), "=r"(r3) : "r"(addr));
}

__device__ __forceinline__ void mma16816(float* c, const uint32_t* a, uint32_t b0, uint32_t b1) {
    asm volatile("mma.sync.aligned.m16n8k16.row.col.f32.f16.f16.f32 "
                 "{%0,%1,%2,%3}, {%4,%5,%6,%7}, {%8,%9}, {%0,%1,%2,%3};"
                 : "+f"(c[0]), "+f"(c[1]), "+f"(c[2]), "+f"(c[3])
                 : "r"(a[0]), "r"(a[1]), "r"(a[2]), "r"(a[3]), "r"(b0), "r"(b1));
}

__device__ __forceinline__ void red_add_v2(float* p, float a, float b) {
    asm volatile("red.global.add.v2.f32 [%0], {%1,%2};" :: "l"(p), "f"(a), "f"(b) : "memory");
}

__device__ __forceinline__ void cp_async16(uint32_t dst, const void* src) {
    asm volatile("cp.async.cg.shared.global [%0], [%1], 16;" :: "r"(dst), "l"(src));
}
__device__ __forceinline__ void cp_commit_wait() {
    asm volatile("cp.async.commit_group;");
    asm volatile("cp.async.wait_group 0;" ::: "memory");
}
__device__ __forceinline__ void pair_bar(int barid) {
    asm volatile("bar.sync %0, 64;" :: "r"(barid) : "memory");
}

// Warp GEMM: C[32 rows x 64 cols] += A(rows rbase.., k 0..127) * W(n0.., kg_w + k)
__device__ __forceinline__ void gemm_pair(float C[2][8][4], uint32_t At_addr, uint32_t W_addr,
                                          int ldw, int rbase, int n0, int lane, int kg_w)
{
    #pragma unroll
    for (int kt = 0; kt < 8; ++kt) {
        uint32_t a[2][4];
        #pragma unroll
        for (int ms = 0; ms < 2; ++ms) {
            int ar = rbase + ms * 16 + (lane & 7) + ((lane >> 3) & 1) * 8;
            int ac = kt * 16 + (lane >> 4) * 8;
            ldsm_x4(a[ms][0], a[ms][1], a[ms][2], a[ms][3],
                    At_addr + (uint32_t)((ar * LDS_A + ac) * 2));
        }
        #pragma unroll
        for (int np = 0; np < 4; ++np) {
            int br = n0 + np * 16 + (lane & 7) + (lane >> 4) * 8;
            int bc = kg_w + kt * 16 + ((lane >> 3) & 1) * 8;
            uint32_t b0, b1, b2, b3;
            ldsm_x4(b0, b1, b2, b3, W_addr + (uint32_t)((br * ldw + bc) * 2));
            mma16816(C[0][2 * np],     a[0], b0, b1);
            mma16816(C[0][2 * np + 1], a[0], b2, b3);
            mma16816(C[1][2 * np],     a[1], b0, b1);
            mma16816(C[1][2 * np + 1], a[1], b2, b3);
        }
    }
}

// ---------------- small kernels ----------------
__global__ void detect_idx_kernel(const unsigned* __restrict__ p) {
    int all0 = 1;
    for (int i = 1; i < 64; i += 2) all0 &= (p[i] == 0u);
    g_idx64 = all0;
}

__global__ void zero_agg_kernel(int n4) {
    int i = blockIdx.x * blockDim.x + threadIdx.x;
    if (i < n4) reinterpret_cast<float4*>(g_agg)[i] = make_float4(0.f, 0.f, 0.f, 0.f);
}

__global__ void prep_h16_kernel(const float* __restrict__ h, int n4) {
    int i = blockIdx.x * blockDim.x + threadIdx.x;
    if (i < n4) {
        float4 v = reinterpret_cast<const float4*>(h)[i];
        __half2 p0 = __floats2half2_rn(v.x, v.y);
        __half2 p1 = __floats2half2_rn(v.z, v.w);
        uint2 pk;
        pk.x = *reinterpret_cast<uint32_t*>(&p0);
        pk.y = *reinterpret_cast<uint32_t*>(&p1);
        reinterpret_cast<uint2*>(g_h16)[i] = pk;
    }
}

#define SMEM_EDGE 175616
#define SMEM_NODE 173056

// ---------------- edge kernel (persistent, 512 threads, warp-pairs) ----------------
__global__ void __launch_bounds__(512, 1)
edge_kernel(const float* __restrict__ coords, const void* __restrict__ eidx_raw,
            const float* __restrict__ W1, const float* __restrict__ b1,
            const float* __restrict__ W2, const float* __restrict__ b2,
            int nE, int nTiles)
{
    extern __shared__ __align__(16) unsigned char smem[];
    __half* W1s = (__half*)smem;                 // 67584
    __half* W2s = (__half*)(smem + 67584);       // 34816 -> 102400
    __half* At  = (__half*)(smem + 102400);      // 256*136*2 = 69632 -> 172032
    float* dist_s = (float*)(smem + 173568);     // 256
    int*   ridx_s = (int*)  (smem + 174592);     // 256

    int tid = threadIdx.x;

    // weights -> SMEM once (fp16); W1 col 256 (dist weight) handled via registers below
    for (int i = tid; i < 128 * 257; i += 512) {
        int n = i / 257, k = i - n * 257;
        if (k < 256) W1s[n * LDS_W1 + k] = __float2half_rn(W1[i]);
    }
    for (int i = tid; i < 128 * 128; i += 512)
        W2s[(i >> 7) * LDS_W2 + (i & 127)] = __float2half_rn(W2[i]);
    __syncthreads();

    const int lane = tid & 31, warp = tid >> 5;
    const int pair = warp >> 1, wsub = warp & 1;
    const int barid = pair + 1;
    const int rbase = pair * 32;
    const int n0 = wsub * 64;
    const bool idx64 = (g_idx64 != 0);

    uint32_t At_addr = (uint32_t)__cvta_generic_to_shared(At);
    uint32_t W1_addr = (uint32_t)__cvta_generic_to_shared(W1s);
    uint32_t W2_addr = (uint32_t)__cvta_generic_to_shared(W2s);

    const int qr = lane >> 2;
    const int qc = (lane & 3) * 2;

    // tile-invariant per-thread constants: dist weight (W1 col 256) + biases, packed half2
    __half2 w1h2[8], b1h2[8], b2h2[8];
    #pragma unroll
    for (int nt = 0; nt < 8; ++nt) {
        int col = n0 + nt * 8 + qc;
        w1h2[nt] = __floats2half2_rn(W1[col * 257 + 256], W1[(col + 1) * 257 + 256]);
        b1h2[nt] = __floats2half2_rn(b1[col], b1[col + 1]);
        b2h2[nt] = __floats2half2_rn(b2[col], b2[col + 1]);
    }

    for (int tile = blockIdx.x; tile < nTiles; tile += gridDim.x) {
        pair_bar(barid);  // previous tile fully consumed (At, dist_s, ridx_s)

        long long e0 = (long long)tile * TILE_E;

        // ---- meta: this warp owns 16 edges (duplicated across lane halves) ----
        int lane16 = lane & 15;
        long long e = e0 + rbase + wsub * 16 + lane16;
        int sidx = 0, ridx = -1;
        if (e < (long long)nE) {
            if (idx64) {
                const long long* p = (const long long*)eidx_raw;
                sidx = (int)p[e]; ridx = (int)p[(long long)nE + e];
            } else {
                const int* p = (const int*)eidx_raw;
                sidx = p[e]; ridx = p[nE + e];
            }
        }
        float dd = 0.f;
        if (ridx >= 0) {
            float dx = coords[sidx * 3 + 0] - coords[ridx * 3 + 0];
            float dy = coords[sidx * 3 + 1] - coords[ridx * 3 + 1];
            float dz = coords[sidx * 3 + 2] - coords[ridx * 3 + 2];
            dd = sqrtf(dx * dx + dy * dy + dz * dz);
        }
        if (lane < 16) {
            int rr = rbase + wsub * 16 + lane;
            dist_s[rr] = dd;
            ridx_s[rr] = ridx;
        }

        float C[2][8][4];
        #pragma unroll
        for (int ms = 0; ms < 2; ++ms)
            #pragma unroll
            for (int nt = 0; nt < 8; ++nt)
                #pragma unroll
                for (int j = 0; j < 4; ++j) C[ms][nt][j] = 0.f;

        // ---- gather sender rows: 16 rows, 16B per lane, 2 rows per instr ----
        {
            int lrow = lane >> 4;            // 0 or 1
            int lcol = (lane & 15) * 8;      // halves
            #pragma unroll
            for (int ri2 = 0; ri2 < 8; ++ri2) {
                int r = ri2 * 2 + lrow;
                int src = __shfl_sync(0xffffffffu, sidx, r);
                int row = rbase + wsub * 16 + r;
                cp_async16(At_addr + (uint32_t)((row * LDS_A + lcol) * 2),
                           g_h16 + (size_t)src * DF + lcol);
            }
        }
        cp_commit_wait();
        pair_bar(barid);

        gemm_pair(C, At_addr, W1_addr, LDS_W1, rbase, n0, lane, 0);
        pair_bar(barid);  // both warps done reading A before overwrite

        // ---- gather receiver rows ----
        {
            int ridx_g = (ridx < 0) ? 0 : ridx;
            int lrow = lane >> 4;
            int lcol = (lane & 15) * 8;
            #pragma unroll
            for (int ri2 = 0; ri2 < 8; ++ri2) {
                int r = ri2 * 2 + lrow;
                int src = __shfl_sync(0xffffffffu, ridx_g, r);
                int row = rbase + wsub * 16 + r;
                cp_async16(At_addr + (uint32_t)((row * LDS_A + lcol) * 2),
                           g_h16 + (size_t)src * DF + lcol);
            }
        }
        cp_commit_wait();
        pair_bar(barid);

        gemm_pair(C, At_addr, W1_addr, LDS_W1, rbase, n0, lane, 128);
        pair_bar(barid);  // both warps done reading A before epilogue overwrite

        // ---- epilogue 1 (half2): x = C + dist*w1_last + b1, SiLU -> A-tile ----
        #pragma unroll
        for (int ms = 0; ms < 2; ++ms) {
            int r0 = rbase + ms * 16 + qr;
            __half2 dA2 = __float2half2_rn(dist_s[r0]);
            __half2 dB2 = __float2half2_rn(dist_s[r0 + 8]);
            #pragma unroll
            for (int nt = 0; nt < 8; ++nt) {
                int col = n0 + nt * 8 + qc;
                __half2 p0 = __floats2half2_rn(C[ms][nt][0], C[ms][nt][1]);
                __half2 p1 = __floats2half2_rn(C[ms][nt][2], C[ms][nt][3]);
                p0 = silu_h2(__hadd2(__hfma2(dA2, w1h2[nt], p0), b1h2[nt]));
                p1 = silu_h2(__hadd2(__hfma2(dB2, w1h2[nt], p1), b1h2[nt]));
                *reinterpret_cast<uint32_t*>(&At[r0 * LDS_A + col])       = *reinterpret_cast<uint32_t*>(&p0);
                *reinterpret_cast<uint32_t*>(&At[(r0 + 8) * LDS_A + col]) = *reinterpret_cast<uint32_t*>(&p1);
                C[ms][nt][0] = 0.f; C[ms][nt][1] = 0.f; C[ms][nt][2] = 0.f; C[ms][nt][3] = 0.f;
            }
        }
        pair_bar(barid);  // full 32x128 layer-1 output visible to both warps

        // ---- GEMM2: K=128 with W2 ----
        gemm_pair(C, At_addr, W2_addr, LDS_W2, rbase, n0, lane, 0);

        // ---- epilogue 2 (half2 silu) then fp32 scatter-add into g_agg ----
        #pragma unroll
        for (int ms = 0; ms < 2; ++ms) {
            int r0 = rbase + ms * 16 + qr;
            int iA = ridx_s[r0], iB = ridx_s[r0 + 8];
            #pragma unroll
            for (int nt = 0; nt < 8; ++nt) {
                int col = n0 + nt * 8 + qc;
                __half2 p0 = silu_h2(__hadd2(__floats2half2_rn(C[ms][nt][0], C[ms][nt][1]), b2h2[nt]));
                __half2 p1 = silu_h2(__hadd2(__floats2half2_rn(C[ms][nt][2], C[ms][nt][3]), b2h2[nt]));
                float2 f0 = __half22float2(p0);
                float2 f1 = __half22float2(p1);
                if (iA >= 0) red_add_v2(&g_agg[(size_t)iA * DF + col], f0.x, f0.y);
                if (iB >= 0) red_add_v2(&g_agg[(size_t)iB * DF + col], f1.x, f1.y);
            }
        }
    }
}

// ---------------- node kernel (persistent, 512 threads, warp-pairs) ----------------
__global__ void __launch_bounds__(512, 1)
node_kernel(const float* __restrict__ h,
            const float* __restrict__ U1, const float* __restrict__ c1,
            const float* __restrict__ U2, const float* __restrict__ c2,
            float* __restrict__ out, int nN, int nTiles)
{
    extern __shared__ __align__(16) unsigned char smem[];
    __half* U1s = (__half*)smem;                 // 67584
    __half* U2s = (__half*)(smem + 67584);       // -> 102400
    __half* At  = (__half*)(smem + 102400);      // -> 172032

    int tid = threadIdx.x;
    for (int i = tid; i < 128 * 256; i += 512)
        U1s[(i >> 8) * LDS_W1 + (i & 255)] = __float2half_rn(U1[i]);
    for (int i = tid; i < 128 * 128; i += 512)
        U2s[(i >> 7) * LDS_W2 + (i & 127)] = __float2half_rn(U2[i]);
    __syncthreads();

    const int lane = tid & 31, warp = tid >> 5;
    const int pair = warp >> 1, wsub = warp & 1;
    const int barid = pair + 1;
    const int rbase = pair * 32;
    const int n0 = wsub * 64;

    uint32_t At_addr = (uint32_t)__cvta_generic_to_shared(At);
    uint32_t U1_addr = (uint32_t)__cvta_generic_to_shared(U1s);
    uint32_t U2_addr = (uint32_t)__cvta_generic_to_shared(U2s);

    const int qr = lane >> 2;
    const int qc = (lane & 3) * 2;

    __half2 c1h2[8];
    float2  c2f2[8];
    #pragma unroll
    for (int nt = 0; nt < 8; ++nt) {
        int col = n0 + nt * 8 + qc;
        c1h2[nt] = __floats2half2_rn(c1[col], c1[col + 1]);
        c2f2[nt] = make_float2(c2[col], c2[col + 1]);
    }

    for (int tile = blockIdx.x; tile < nTiles; tile += gridDim.x) {
        pair_bar(barid);
        int tbase = tile * TILE_E;

        float C[2][8][4];
        #pragma unroll
        for (int ms = 0; ms < 2; ++ms)
            #pragma unroll
            for (int nt = 0; nt < 8; ++nt)
                #pragma unroll
                for (int j = 0; j < 4; ++j) C[ms][nt][j] = 0.f;

        // ---- gather h rows (fp16 table, 16B cp.async) ----
        {
            int lrow = lane >> 4;
            int lcol = (lane & 15) * 8;
            #pragma unroll
            for (int ri2 = 0; ri2 < 8; ++ri2) {
                int r = ri2 * 2 + lrow;
                int node = tbase + rbase + wsub * 16 + r;
                if (node >= nN) node = nN - 1;
                int row = rbase + wsub * 16 + r;
                cp_async16(At_addr + (uint32_t)((row * LDS_A + lcol) * 2),
                           g_h16 + (size_t)node * DF + lcol);
            }
        }
        cp_commit_wait();
        pair_bar(barid);

        gemm_pair(C, At_addr, U1_addr, LDS_W1, rbase, n0, lane, 0);
        pair_bar(barid);

        // ---- gather agg rows (fp32 -> fp16) ----
        #pragma unroll 4
        for (int ri = 0; ri < 16; ++ri) {
            int node = tbase + rbase + wsub * 16 + ri;
            if (node >= nN) node = nN - 1;
            int row = rbase + wsub * 16 + ri;
            float4 v = *reinterpret_cast<const float4*>(g_agg + (size_t)node * DF + lane * 4);
            __half2 p0 = __floats2half2_rn(v.x, v.y);
            __half2 p1 = __floats2half2_rn(v.z, v.w);
            uint2 pk;
            pk.x = *reinterpret_cast<uint32_t*>(&p0);
            pk.y = *reinterpret_cast<uint32_t*>(&p1);
            *reinterpret_cast<uint2*>(&At[row * LDS_A + lane * 4]) = pk;
        }
        __syncwarp();
        pair_bar(barid);

        gemm_pair(C, At_addr, U1_addr, LDS_W1, rbase, n0, lane, 128);
        pair_bar(barid);

        // ---- epilogue 1: SiLU(C + c1) -> A-tile (half2) ----
        #pragma unroll
        for (int ms = 0; ms < 2; ++ms) {
            int r0 = rbase + ms * 16 + qr;
            #pragma unroll
            for (int nt = 0; nt < 8; ++nt) {
                int col = n0 + nt * 8 + qc;
                __half2 p0 = silu_h2(__hadd2(__floats2half2_rn(C[ms][nt][0], C[ms][nt][1]), c1h2[nt]));
                __half2 p1 = silu_h2(__hadd2(__floats2half2_rn(C[ms][nt][2], C[ms][nt][3]), c1h2[nt]));
                *reinterpret_cast<uint32_t*>(&At[r0 * LDS_A + col])       = *reinterpret_cast<uint32_t*>(&p0);
                *reinterpret_cast<uint32_t*>(&At[(r0 + 8) * LDS_A + col]) = *reinterpret_cast<uint32_t*>(&p1);
                C[ms][nt][0] = 0.f; C[ms][nt][1] = 0.f; C[ms][nt][2] = 0.f; C[ms][nt][3] = 0.f;
            }
        }
        pair_bar(barid);

        gemm_pair(C, At_addr, U2_addr, LDS_W2, rbase, n0, lane, 0);

        // ---- epilogue 2: out = h + (C + c2)  (fp32, exact) ----
        #pragma unroll
        for (int ms = 0; ms < 2; ++ms) {
            int r0 = rbase + ms * 16 + qr;
            int nodeA = tbase + r0;
            int nodeB = nodeA + 8;
            #pragma unroll
            for (int nt = 0; nt < 8; ++nt) {
                int col = n0 + nt * 8 + qc;
                if (nodeA < nN) {
                    float2 hv = *reinterpret_cast<const float2*>(h + (size_t)nodeA * DF + col);
                    float2 o;
                    o.x = hv.x + C[ms][nt][0] + c2f2[nt].x;
                    o.y = hv.y + C[ms][nt][1] + c2f2[nt].y;
                    *reinterpret_cast<float2*>(out + (size_t)nodeA * DF + col) = o;
                }
                if (nodeB < nN) {
                    float2 hv = *reinterpret_cast<const float2*>(h + (size_t)nodeB * DF + col);
                    float2 o;
                    o.x = hv.x + C[ms][nt][2] + c2f2[nt].x;
                    o.y = hv.y + C[ms][nt][3] + c2f2[nt].y;
                    *reinterpret_cast<float2*>(out + (size_t)nodeB * DF + col) = o;
                }
            }
        }
    }
}

// ---------------- launch ----------------
extern "C" void kernel_launch(void* const* d_in, const int* in_sizes, int n_in,
                              void* d_out, int out_size)
{
    const float* h      = (const float*)d_in[0];
    const float* coords = (const float*)d_in[1];
    const void*  eidx   = d_in[2];
    const float* W1     = (const float*)d_in[3];
    const float* b1     = (const float*)d_in[4];
    const float* W2     = (const float*)d_in[5];
    const float* b2     = (const float*)d_in[6];
    const float* U1     = (const float*)d_in[7];
    const float* c1     = (const float*)d_in[8];
    const float* U2     = (const float*)d_in[9];
    const float* c2     = (const float*)d_in[10];
    float* out = (float*)d_out;

    int nN = in_sizes[0] / DF;
    int nE = in_sizes[2] / 2;

    int sms = 148;
    cudaDeviceGetAttribute(&sms, cudaDevAttrMultiProcessorCount, 0);

    cudaFuncSetAttribute(edge_kernel, cudaFuncAttributeMaxDynamicSharedMemorySize, SMEM_EDGE);
    cudaFuncSetAttribute(node_kernel, cudaFuncAttributeMaxDynamicSharedMemorySize, SMEM_NODE);

    detect_idx_kernel<<<1, 1>>>((const unsigned*)eidx);

    int n4 = nN * DF / 4;
    prep_h16_kernel<<<(n4 + 255) / 256, 256>>>(h, n4);
    zero_agg_kernel<<<(n4 + 255) / 256, 256>>>(n4);

    int nTilesE = (nE + TILE_E - 1) / TILE_E;
    int gE = (sms < nTilesE) ? sms : nTilesE;
    edge_kernel<<<gE, 512, SMEM_EDGE>>>(coords, eidx, W1, b1, W2, b2, nE, nTilesE);

    int nTilesN = (nN + TILE_E - 1) / TILE_E;
    int gN = (sms < nTilesN) ? sms : nTilesN;
    node_kernel<<<gN, 512, SMEM_NODE>>>(h, U1, c1, U2, c2, out, nN, nTilesN);
}